// round 1
// baseline (speedup 1.0000x reference)
#include <cuda_runtime.h>
#include <math.h>

#define TDIM 2048
#define CDIM 1024
#define HN   8
#define NW   8192          // output cols per weight matrix
#define WIN  448           // decay window (gamma^448 ~ 6.6e-7)
#define KQ   512           // q-range per t-tile = TT + WIN
#define TT   64            // t tile
#define NTIL 32            // TDIM / TT
#define GAMMA 0.96875f

// scratch: [w][h][t][c] fp32 QKV (192MB) + banded scores (33.5MB)
__device__ float g_qkv[(size_t)3 * HN * TDIM * CDIM];
__device__ float g_P[(size_t)HN * NTIL * TT * KQ];

// ---------------------------------------------------------------------------
// Kernel 1: projections.  C[t,n] = sum_k X[t,k] W[k,n], written to
// g_qkv[z][n>>10][t][n&1023].  128x128x16 tiles, 256 thr, 8x8 micro-tile.
// ---------------------------------------------------------------------------
__global__ __launch_bounds__(256) void proj_kernel(
    const float* __restrict__ X,
    const float* __restrict__ Wq,
    const float* __restrict__ Wk,
    const float* __restrict__ Wv)
{
    const int z  = blockIdx.z;
    const float* W = (z == 0) ? Wq : ((z == 1) ? Wk : Wv);
    const int n0 = blockIdx.x * 128;
    const int m0 = blockIdx.y * 128;

    __shared__ float Xs[16][132];
    __shared__ float Ws[16][128];

    const int tid = threadIdx.x;
    const int ty  = tid >> 4;      // 0..15 -> m
    const int tx  = tid & 15;      // 0..15 -> n

    float acc[8][8];
#pragma unroll
    for (int i = 0; i < 8; i++)
#pragma unroll
        for (int j = 0; j < 8; j++) acc[i][j] = 0.f;

    const int xr = tid >> 2;           // 0..63
    const int xc = (tid & 3) * 4;      // 0,4,8,12
    const int wr = tid >> 5;           // 0..7
    const int wc = (tid & 31) * 4;     // 0..124

    for (int k0 = 0; k0 < CDIM; k0 += 16) {
#pragma unroll
        for (int it = 0; it < 2; it++) {
            int row = xr + it * 64;
            float4 v = *(const float4*)(X + (size_t)(m0 + row) * CDIM + k0 + xc);
            Xs[xc + 0][row] = v.x; Xs[xc + 1][row] = v.y;
            Xs[xc + 2][row] = v.z; Xs[xc + 3][row] = v.w;
        }
#pragma unroll
        for (int it = 0; it < 2; it++) {
            int row = wr + it * 8;
            *(float4*)(&Ws[row][wc]) =
                *(const float4*)(W + (size_t)(k0 + row) * NW + n0 + wc);
        }
        __syncthreads();
#pragma unroll
        for (int k = 0; k < 16; k++) {
            float a[8], b[8];
            *(float4*)(a)     = *(const float4*)(&Xs[k][ty * 4]);
            *(float4*)(a + 4) = *(const float4*)(&Xs[k][ty * 4 + 64]);
            *(float4*)(b)     = *(const float4*)(&Ws[k][tx * 4]);
            *(float4*)(b + 4) = *(const float4*)(&Ws[k][tx * 4 + 64]);
#pragma unroll
            for (int i = 0; i < 8; i++)
#pragma unroll
                for (int j = 0; j < 8; j++) acc[i][j] += a[i] * b[j];
        }
        __syncthreads();
    }

    float* base = g_qkv + (size_t)z * HN * TDIM * CDIM;
#pragma unroll
    for (int i = 0; i < 8; i++) {
        int m = m0 + ty * 4 + ((i < 4) ? i : (60 + i));  // i>=4 -> +64+(i-4)
#pragma unroll
        for (int jh = 0; jh < 2; jh++) {
            int n = n0 + tx * 4 + jh * 64;
            int h = n >> 10, c = n & 1023;
            float4 v = make_float4(acc[i][jh * 4 + 0], acc[i][jh * 4 + 1],
                                   acc[i][jh * 4 + 2], acc[i][jh * 4 + 3]);
            *(float4*)(base + ((size_t)h * TDIM + m) * CDIM + c) = v;
        }
    }
}

// ---------------------------------------------------------------------------
// Kernel 2: in-place RoPE (Q,K only; first 64 dims) + SiLU (all).
// One thread per adjacent pair (2*c2, 2*c2+1).
// ---------------------------------------------------------------------------
__global__ void rope_silu_kernel()
{
    size_t idx = (size_t)blockIdx.x * blockDim.x + threadIdx.x;
    const size_t total = (size_t)3 * HN * TDIM * (CDIM / 2);
    if (idx >= total) return;

    int c2 = (int)(idx & (CDIM / 2 - 1));        // 9 bits
    int t  = (int)((idx >> 9) & (TDIM - 1));     // 11 bits
    int hw = (int)(idx >> 20);
    int w  = hw >> 3;

    float2 v = *(float2*)(g_qkv + idx * 2);

    if (w < 2 && c2 < 32) {
        // inv_freq computed in double, then f32 multiply like the reference
        float invf = (float)exp(-((double)(2 * c2) / 64.0) * log(10000.0));
        float ang = (float)t * invf;
        float sn, cs;
        sincosf(ang, &sn, &cs);
        float y0 = v.x * cs - v.y * sn;
        float y1 = v.y * cs + v.x * sn;
        v.x = y0; v.y = y1;
    }
    v.x = v.x / (1.f + expf(-v.x));
    v.y = v.y / (1.f + expf(-v.y));
    *(float2*)(g_qkv + idx * 2) = v;
}

// ---------------------------------------------------------------------------
// Kernel 3: banded scores.  P[h,tile,m,n] = gamma^(q-t) * (K[t] . Q[q]),
// t = t0+m, q = t0+n (n in [0,512)), masked to 0 <= q-t < WIN, q < T.
// M=64, N=128 per block (grid.x covers n in 4 chunks), K=1024.
// ---------------------------------------------------------------------------
__global__ __launch_bounds__(256) void qk_kernel()
{
    const int h    = blockIdx.z;
    const int tile = blockIdx.y;
    const int t0   = tile * TT;
    const int q0   = t0 + blockIdx.x * 128;

    const float* Qp = g_qkv + (size_t)(0 * HN + h) * TDIM * CDIM;
    const float* Kp = g_qkv + (size_t)(1 * HN + h) * TDIM * CDIM;

    __shared__ float Ks[16][68];
    __shared__ float Qs[16][132];

    const int tid = threadIdx.x;
    const int ty = tid >> 4, tx = tid & 15;
    const int lr = tid >> 2;           // 0..63
    const int lc = (tid & 3) * 4;      // 0,4,8,12

    float acc[4][8];
#pragma unroll
    for (int i = 0; i < 4; i++)
#pragma unroll
        for (int j = 0; j < 8; j++) acc[i][j] = 0.f;

    for (int d0 = 0; d0 < CDIM; d0 += 16) {
        {
            float4 v = *(const float4*)(Kp + (size_t)(t0 + lr) * CDIM + d0 + lc);
            Ks[lc + 0][lr] = v.x; Ks[lc + 1][lr] = v.y;
            Ks[lc + 2][lr] = v.z; Ks[lc + 3][lr] = v.w;
        }
#pragma unroll
        for (int it = 0; it < 2; it++) {
            int row = lr + it * 64;
            int q = q0 + row;
            float4 v = make_float4(0.f, 0.f, 0.f, 0.f);
            if (q < TDIM)
                v = *(const float4*)(Qp + (size_t)q * CDIM + d0 + lc);
            Qs[lc + 0][row] = v.x; Qs[lc + 1][row] = v.y;
            Qs[lc + 2][row] = v.z; Qs[lc + 3][row] = v.w;
        }
        __syncthreads();
#pragma unroll
        for (int k = 0; k < 16; k++) {
            float a[4], b[8];
            *(float4*)(a)     = *(const float4*)(&Ks[k][ty * 4]);
            *(float4*)(b)     = *(const float4*)(&Qs[k][tx * 8]);
            *(float4*)(b + 4) = *(const float4*)(&Qs[k][tx * 8 + 4]);
#pragma unroll
            for (int i = 0; i < 4; i++)
#pragma unroll
                for (int j = 0; j < 8; j++) acc[i][j] += a[i] * b[j];
        }
        __syncthreads();
    }

    const float lg = log2f(GAMMA);
#pragma unroll
    for (int i = 0; i < 4; i++) {
        int t = t0 + ty * 4 + i;
        float vals[8];
#pragma unroll
        for (int j = 0; j < 8; j++) {
            int q = q0 + tx * 8 + j;
            int wd = q - t;
            float val = 0.f;
            if (wd >= 0 && wd < WIN && q < TDIM)
                val = acc[i][j] * exp2f((float)wd * lg);
            vals[j] = val;
        }
        size_t rowbase = (((size_t)h * NTIL + tile) * TT + (ty * 4 + i)) * KQ
                         + (size_t)blockIdx.x * 128 + tx * 8;
        *(float4*)(g_P + rowbase)     = *(float4*)(vals);
        *(float4*)(g_P + rowbase + 4) = *(float4*)(vals + 4);
    }
}

// ---------------------------------------------------------------------------
// Kernel 4: out[t,c] = sum_h sum_n P[h,tile,t-t0,n] * V[h, t0+n, c]
// M=64, N=128 per block, K = 8*512 = 4096.
// ---------------------------------------------------------------------------
__global__ __launch_bounds__(256) void av_kernel(float* __restrict__ out)
{
    const int tile = blockIdx.y;
    const int t0   = tile * TT;
    const int c0   = blockIdx.x * 128;

    __shared__ float As[16][68];
    __shared__ float Bs[16][128];

    const int tid = threadIdx.x;
    const int ty = tid >> 4, tx = tid & 15;
    const int ar = tid >> 2;           // 0..63
    const int ac = (tid & 3) * 4;
    const int br = tid >> 5;           // 0..7
    const int bc = (tid & 31) * 4;

    float acc[4][8];
#pragma unroll
    for (int i = 0; i < 4; i++)
#pragma unroll
        for (int j = 0; j < 8; j++) acc[i][j] = 0.f;

    for (int kk = 0; kk < HN * KQ; kk += 16) {
        int h  = kk >> 9;
        int nb = kk & 511;
        {
            float4 v = *(const float4*)(g_P +
                (((size_t)h * NTIL + tile) * TT + ar) * KQ + nb + ac);
            As[ac + 0][ar] = v.x; As[ac + 1][ar] = v.y;
            As[ac + 2][ar] = v.z; As[ac + 3][ar] = v.w;
        }
        const float* Vp = g_qkv + (size_t)(2 * HN + h) * TDIM * CDIM;
#pragma unroll
        for (int it = 0; it < 2; it++) {
            int r = br + it * 8;
            int vrow = t0 + nb + r;
            float4 v = make_float4(0.f, 0.f, 0.f, 0.f);
            if (vrow < TDIM)
                v = *(const float4*)(Vp + (size_t)vrow * CDIM + c0 + bc);
            *(float4*)(&Bs[r][bc]) = v;
        }
        __syncthreads();
#pragma unroll
        for (int k = 0; k < 16; k++) {
            float a[4], b[8];
            *(float4*)(a)     = *(const float4*)(&As[k][ty * 4]);
            *(float4*)(b)     = *(const float4*)(&Bs[k][tx * 8]);
            *(float4*)(b + 4) = *(const float4*)(&Bs[k][tx * 8 + 4]);
#pragma unroll
            for (int i = 0; i < 4; i++)
#pragma unroll
                for (int j = 0; j < 8; j++) acc[i][j] += a[i] * b[j];
        }
        __syncthreads();
    }

#pragma unroll
    for (int i = 0; i < 4; i++) {
        int t = t0 + ty * 4 + i;
        float* o = out + (size_t)t * CDIM + c0 + tx * 8;
        *(float4*)(o)     = make_float4(acc[i][0], acc[i][1], acc[i][2], acc[i][3]);
        *(float4*)(o + 4) = make_float4(acc[i][4], acc[i][5], acc[i][6], acc[i][7]);
    }
}

// ---------------------------------------------------------------------------
// Kernel 5: in-place GroupNorm over C=1024, 16 groups of 64, per row t.
// ---------------------------------------------------------------------------
__global__ __launch_bounds__(256) void gn_kernel(
    float* __restrict__ out,
    const float* __restrict__ wgt,
    const float* __restrict__ bias)
{
    const int t = blockIdx.x;
    const int tid = threadIdx.x;

    float4 v = *(float4*)(out + (size_t)t * CDIM + tid * 4);
    float s  = v.x + v.y + v.z + v.w;
    float sq = v.x * v.x + v.y * v.y + v.z * v.z + v.w * v.w;

#pragma unroll
    for (int off = 8; off > 0; off >>= 1) {
        s  += __shfl_down_sync(0xffffffffu, s,  off, 16);
        sq += __shfl_down_sync(0xffffffffu, sq, off, 16);
    }
    s  = __shfl_sync(0xffffffffu, s,  0, 16);
    sq = __shfl_sync(0xffffffffu, sq, 0, 16);

    float mean = s * (1.f / 64.f);
    float var  = sq * (1.f / 64.f) - mean * mean;
    float rs   = rsqrtf(var + 1e-5f);

    float4 w4 = *(const float4*)(wgt + tid * 4);
    float4 b4 = *(const float4*)(bias + tid * 4);
    v.x = (v.x - mean) * rs * w4.x + b4.x;
    v.y = (v.y - mean) * rs * w4.y + b4.y;
    v.z = (v.z - mean) * rs * w4.z + b4.z;
    v.w = (v.w - mean) * rs * w4.w + b4.w;
    *(float4*)(out + (size_t)t * CDIM + tid * 4) = v;
}

// ---------------------------------------------------------------------------
extern "C" void kernel_launch(void* const* d_in, const int* in_sizes, int n_in,
                              void* d_out, int out_size)
{
    const float* X  = (const float*)d_in[0];
    const float* Wq = (const float*)d_in[1];
    const float* Wk = (const float*)d_in[2];
    const float* Wv = (const float*)d_in[3];
    const float* gw = (const float*)d_in[4];
    const float* gb = (const float*)d_in[5];
    float* out = (float*)d_out;

    proj_kernel<<<dim3(64, 16, 3), 256>>>(X, Wq, Wk, Wv);

    {
        size_t total = (size_t)3 * HN * TDIM * (CDIM / 2);
        rope_silu_kernel<<<(unsigned)((total + 255) / 256), 256>>>();
    }

    qk_kernel<<<dim3(4, 32, 8), 256>>>();
    av_kernel<<<dim3(8, 32), 256>>>(out);
    gn_kernel<<<TDIM, 256>>>(out, gw, gb);
}

// round 3
// speedup vs baseline: 1.5420x; 1.5420x over previous
#include <cuda_runtime.h>
#include <cuda_bf16.h>
#include <math.h>
#include <stdint.h>

#define TDIM 2048
#define CDIM 1024
#define HN   8
#define NW   8192
#define WIN  448
#define KQ   512
#define TT   64
#define NTIL 32
#define GAMMA 0.96875f

// scratch
__device__ float g_qkv[(size_t)3 * HN * TDIM * CDIM];          // 192 MB
__device__ float g_P[(size_t)HN * NTIL * TT * KQ];             // 33.5 MB
__device__ __nv_bfloat16 g_Xhi[(size_t)TDIM * CDIM];
__device__ __nv_bfloat16 g_Xlo[(size_t)TDIM * CDIM];
__device__ __nv_bfloat16 g_Wthi[(size_t)3 * NW * CDIM];        // [z][n][k]
__device__ __nv_bfloat16 g_Wtlo[(size_t)3 * NW * CDIM];

// ---------------------------------------------------------------------------
#define CP16(dst, src) \
    asm volatile("cp.async.cg.shared.global [%0], [%1], 16;" :: "r"(dst), "l"(src))
#define CP_COMMIT() asm volatile("cp.async.commit_group;" ::: "memory")
#define CP_WAIT1()  asm volatile("cp.async.wait_group 1;" ::: "memory")
#define CP_WAIT0()  asm volatile("cp.async.wait_group 0;" ::: "memory")

__device__ __forceinline__ uint32_t smem_u32(const void* p) {
    uint32_t a;
    asm("{ .reg .u64 t; cvta.to.shared.u64 t, %1; cvt.u32.u64 %0, t; }"
        : "=r"(a) : "l"(p));
    return a;
}

__device__ __forceinline__ void mma_bf16(float c[4], const uint32_t a[4],
                                         const uint32_t b[2]) {
    asm volatile(
        "mma.sync.aligned.m16n8k16.row.col.f32.bf16.bf16.f32 "
        "{%0,%1,%2,%3}, {%4,%5,%6,%7}, {%8,%9}, {%0,%1,%2,%3};"
        : "+f"(c[0]), "+f"(c[1]), "+f"(c[2]), "+f"(c[3])
        : "r"(a[0]), "r"(a[1]), "r"(a[2]), "r"(a[3]), "r"(b[0]), "r"(b[1]));
}

// ---------------------------------------------------------------------------
// Prep: split X into hi/lo bf16
// ---------------------------------------------------------------------------
__global__ __launch_bounds__(256) void prep_x(const float* __restrict__ X)
{
    int i = blockIdx.x * 256 + threadIdx.x;
    float4 v = ((const float4*)X)[i];
    __nv_bfloat16 h[4], l[4];
    float f[4] = {v.x, v.y, v.z, v.w};
#pragma unroll
    for (int j = 0; j < 4; j++) {
        h[j] = __float2bfloat16(f[j]);
        l[j] = __float2bfloat16(f[j] - __bfloat162float(h[j]));
    }
    ((ushort4*)g_Xhi)[i] = make_ushort4(*(unsigned short*)&h[0], *(unsigned short*)&h[1],
                                        *(unsigned short*)&h[2], *(unsigned short*)&h[3]);
    ((ushort4*)g_Xlo)[i] = make_ushort4(*(unsigned short*)&l[0], *(unsigned short*)&l[1],
                                        *(unsigned short*)&l[2], *(unsigned short*)&l[3]);
}

// ---------------------------------------------------------------------------
// Prep: transpose W [K,N] -> Wt [N,K], split hi/lo bf16
// ---------------------------------------------------------------------------
__global__ __launch_bounds__(256) void prep_w(
    const float* __restrict__ Wq, const float* __restrict__ Wk,
    const float* __restrict__ Wv)
{
    const int z = blockIdx.z;
    const float* W = (z == 0) ? Wq : ((z == 1) ? Wk : Wv);
    const int n0 = blockIdx.x * 32;
    const int k0 = blockIdx.y * 32;

    __shared__ float t[32][33];
    const int tx = threadIdx.x, ty = threadIdx.y;
#pragma unroll
    for (int j = 0; j < 4; j++)
        t[ty + 8 * j][tx] = W[(size_t)(k0 + ty + 8 * j) * NW + n0 + tx];
    __syncthreads();
#pragma unroll
    for (int j = 0; j < 4; j++) {
        float v = t[tx][ty + 8 * j];
        __nv_bfloat16 h = __float2bfloat16(v);
        __nv_bfloat16 l = __float2bfloat16(v - __bfloat162float(h));
        size_t o = ((size_t)z * NW + n0 + ty + 8 * j) * CDIM + k0 + tx;
        g_Wthi[o] = h;
        g_Wtlo[o] = l;
    }
}

// ---------------------------------------------------------------------------
// Projection via mma.sync bf16 3-term split.
// CTA tile M=128, N=256, K-stage 32; warps 2(m) x 4(n), warp tile 64x64.
// smem stage layout (stride 80B rows, bank-conflict-free):
//   Ahi [128][40bf16] @0      (10240 B)
//   Alo                @10240
//   Bhi [256][40bf16] @20480  (20480 B)   (B stored [n][k])
//   Blo                @40960
// stage size 61440, double buffered -> 122880 B dynamic smem.
// ---------------------------------------------------------------------------
#define PSTAGE 61440
#define SMEM_PROJ (2 * PSTAGE)

__device__ __forceinline__ void proj_load_stage(
    uint32_t stb, int tid, int m0, int zn0, int k0)
{
#pragma unroll
    for (int i = 0; i < 12; i++) {
        const int c = tid + i * 256;
        if (c < 1024) {                      // A chunks (i = 0..3)
            const int mat = c >> 9;
            const int rem = c & 511;
            const int row = rem >> 2;
            const int ch  = rem & 3;
            const __nv_bfloat16* src = (mat ? g_Xlo : g_Xhi)
                + (size_t)(m0 + row) * CDIM + k0 + ch * 8;
            CP16(stb + mat * 10240 + row * 80 + ch * 16, src);
        } else {                             // B chunks (i = 4..11)
            const int cb  = c - 1024;
            const int mat = cb >> 10;
            const int rem = cb & 1023;
            const int row = rem >> 2;
            const int ch  = rem & 3;
            const __nv_bfloat16* src = (mat ? g_Wtlo : g_Wthi)
                + (size_t)(zn0 + row) * CDIM + k0 + ch * 8;
            CP16(stb + 20480 + mat * 20480 + row * 80 + ch * 16, src);
        }
    }
}

__global__ __launch_bounds__(256, 1) void proj_mma()
{
    extern __shared__ char smem[];
    const uint32_t sb = smem_u32(smem);
    const int tid = threadIdx.x;
    const int wid = tid >> 5;
    const int lane = tid & 31;
    const int wm = wid & 1, wn = wid >> 1;
    const int g = lane >> 2, t4 = lane & 3;

    const int m0 = blockIdx.x * 128;
    const int n0 = blockIdx.y * 256;
    const int z  = blockIdx.z;
    const int zn0 = z * NW + n0;

    float acc[4][8][4];
#pragma unroll
    for (int i = 0; i < 4; i++)
#pragma unroll
        for (int j = 0; j < 8; j++)
#pragma unroll
            for (int q = 0; q < 4; q++) acc[i][j][q] = 0.f;

    proj_load_stage(sb, tid, m0, zn0, 0);
    CP_COMMIT();

#pragma unroll 1
    for (int s = 0; s < 32; s++) {
        const char* st = smem + (s & 1) * PSTAGE;
        if (s + 1 < 32) {
            proj_load_stage(sb + ((s + 1) & 1) * PSTAGE, tid, m0, zn0, (s + 1) * 32);
            CP_COMMIT();
            CP_WAIT1();
        } else {
            CP_WAIT0();
        }
        __syncthreads();

        const char* Ah = st;
        const char* Al = st + 10240;
        const char* Bh = st + 20480;
        const char* Bl = st + 40960;

#pragma unroll
        for (int kk = 0; kk < 32; kk += 16) {
            uint32_t ah[4][4], al[4][4];
#pragma unroll
            for (int i = 0; i < 4; i++) {
                const int b0 = (wm * 64 + i * 16 + g) * 80 + kk * 2 + t4 * 4;
                ah[i][0] = *(const uint32_t*)(Ah + b0);
                ah[i][1] = *(const uint32_t*)(Ah + b0 + 640);
                ah[i][2] = *(const uint32_t*)(Ah + b0 + 16);
                ah[i][3] = *(const uint32_t*)(Ah + b0 + 656);
                al[i][0] = *(const uint32_t*)(Al + b0);
                al[i][1] = *(const uint32_t*)(Al + b0 + 640);
                al[i][2] = *(const uint32_t*)(Al + b0 + 16);
                al[i][3] = *(const uint32_t*)(Al + b0 + 656);
            }
#pragma unroll
            for (int jj = 0; jj < 2; jj++) {
                uint32_t bh[4][2], bl[4][2];
#pragma unroll
                for (int j = 0; j < 4; j++) {
                    const int bb = (wn * 64 + jj * 32 + j * 8 + g) * 80 + kk * 2 + t4 * 4;
                    bh[j][0] = *(const uint32_t*)(Bh + bb);
                    bh[j][1] = *(const uint32_t*)(Bh + bb + 16);
                    bl[j][0] = *(const uint32_t*)(Bl + bb);
                    bl[j][1] = *(const uint32_t*)(Bl + bb + 16);
                }
#pragma unroll
                for (int i = 0; i < 4; i++)
#pragma unroll
                    for (int j = 0; j < 4; j++) {
                        float* c = acc[i][jj * 4 + j];
                        mma_bf16(c, ah[i], bh[j]);
                        mma_bf16(c, ah[i], bl[j]);
                        mma_bf16(c, al[i], bh[j]);
                    }
            }
        }
        __syncthreads();
    }

    // epilogue: acc -> g_qkv fp32 [z][h][t][c]
    const int h  = n0 >> 10;
    const int cb = (n0 & 1023) + wn * 64 + 2 * t4;
    float* ob = g_qkv + ((size_t)z * HN + h) * TDIM * CDIM;
#pragma unroll
    for (int i = 0; i < 4; i++) {
        const int r0 = m0 + wm * 64 + i * 16 + g;
#pragma unroll
        for (int j = 0; j < 8; j++) {
            const int col = cb + j * 8;
            *(float2*)(ob + (size_t)r0 * CDIM + col) =
                make_float2(acc[i][j][0], acc[i][j][1]);
            *(float2*)(ob + (size_t)(r0 + 8) * CDIM + col) =
                make_float2(acc[i][j][2], acc[i][j][3]);
        }
    }
}

// ---------------------------------------------------------------------------
// Kernel 2: in-place RoPE (Q,K only; first 64 dims) + SiLU (all).
// ---------------------------------------------------------------------------
__global__ void rope_silu_kernel()
{
    size_t idx = (size_t)blockIdx.x * blockDim.x + threadIdx.x;
    const size_t total = (size_t)3 * HN * TDIM * (CDIM / 2);
    if (idx >= total) return;

    int c2 = (int)(idx & (CDIM / 2 - 1));
    int t  = (int)((idx >> 9) & (TDIM - 1));
    int hw = (int)(idx >> 20);
    int w  = hw >> 3;

    float2 v = *(float2*)(g_qkv + idx * 2);

    if (w < 2 && c2 < 32) {
        float invf = (float)exp(-((double)(2 * c2) / 64.0) * log(10000.0));
        float ang = (float)t * invf;
        float sn, cs;
        sincosf(ang, &sn, &cs);
        float y0 = v.x * cs - v.y * sn;
        float y1 = v.y * cs + v.x * sn;
        v.x = y0; v.y = y1;
    }
    v.x = v.x / (1.f + expf(-v.x));
    v.y = v.y / (1.f + expf(-v.y));
    *(float2*)(g_qkv + idx * 2) = v;
}

// ---------------------------------------------------------------------------
// Kernel 3: banded scores.
// ---------------------------------------------------------------------------
__global__ __launch_bounds__(256) void qk_kernel()
{
    const int h    = blockIdx.z;
    const int tile = blockIdx.y;
    const int t0   = tile * TT;
    const int q0   = t0 + blockIdx.x * 128;

    const float* Qp = g_qkv + (size_t)(0 * HN + h) * TDIM * CDIM;
    const float* Kp = g_qkv + (size_t)(1 * HN + h) * TDIM * CDIM;

    __shared__ float Ks[16][68];
    __shared__ float Qs[16][132];

    const int tid = threadIdx.x;
    const int ty = tid >> 4, tx = tid & 15;
    const int lr = tid >> 2;
    const int lc = (tid & 3) * 4;

    float acc[4][8];
#pragma unroll
    for (int i = 0; i < 4; i++)
#pragma unroll
        for (int j = 0; j < 8; j++) acc[i][j] = 0.f;

    for (int d0 = 0; d0 < CDIM; d0 += 16) {
        {
            float4 v = *(const float4*)(Kp + (size_t)(t0 + lr) * CDIM + d0 + lc);
            Ks[lc + 0][lr] = v.x; Ks[lc + 1][lr] = v.y;
            Ks[lc + 2][lr] = v.z; Ks[lc + 3][lr] = v.w;
        }
#pragma unroll
        for (int it = 0; it < 2; it++) {
            int row = lr + it * 64;
            int q = q0 + row;
            float4 v = make_float4(0.f, 0.f, 0.f, 0.f);
            if (q < TDIM)
                v = *(const float4*)(Qp + (size_t)q * CDIM + d0 + lc);
            Qs[lc + 0][row] = v.x; Qs[lc + 1][row] = v.y;
            Qs[lc + 2][row] = v.z; Qs[lc + 3][row] = v.w;
        }
        __syncthreads();
#pragma unroll
        for (int k = 0; k < 16; k++) {
            float a[4], b[8];
            *(float4*)(a)     = *(const float4*)(&Ks[k][ty * 4]);
            *(float4*)(b)     = *(const float4*)(&Qs[k][tx * 8]);
            *(float4*)(b + 4) = *(const float4*)(&Qs[k][tx * 8 + 4]);
#pragma unroll
            for (int i = 0; i < 4; i++)
#pragma unroll
                for (int j = 0; j < 8; j++) acc[i][j] += a[i] * b[j];
        }
        __syncthreads();
    }

    const float lg = log2f(GAMMA);
#pragma unroll
    for (int i = 0; i < 4; i++) {
        int t = t0 + ty * 4 + i;
        float vals[8];
#pragma unroll
        for (int j = 0; j < 8; j++) {
            int q = q0 + tx * 8 + j;
            int wd = q - t;
            float val = 0.f;
            if (wd >= 0 && wd < WIN && q < TDIM)
                val = acc[i][j] * exp2f((float)wd * lg);
            vals[j] = val;
        }
        size_t rowbase = (((size_t)h * NTIL + tile) * TT + (ty * 4 + i)) * KQ
                         + (size_t)blockIdx.x * 128 + tx * 8;
        *(float4*)(g_P + rowbase)     = *(float4*)(vals);
        *(float4*)(g_P + rowbase + 4) = *(float4*)(vals + 4);
    }
}

// ---------------------------------------------------------------------------
// Kernel 4: out[t,c] = sum_h sum_n P[h,tile,t-t0,n] * V[h, t0+n, c]
// M=64, N=64 per block (more CTAs -> better occupancy), K = 4096.
// ---------------------------------------------------------------------------
__global__ __launch_bounds__(256) void av_kernel(float* __restrict__ out)
{
    const int tile = blockIdx.y;
    const int t0   = tile * TT;
    const int c0   = blockIdx.x * 64;

    __shared__ float As[16][68];
    __shared__ float Bs[16][68];

    const int tid = threadIdx.x;
    const int ty = tid >> 4, tx = tid & 15;
    const int ar = tid >> 2;
    const int ac = (tid & 3) * 4;
    const int br = tid >> 4;
    const int bc = (tid & 15) * 4;

    float acc[4][4];
#pragma unroll
    for (int i = 0; i < 4; i++)
#pragma unroll
        for (int j = 0; j < 4; j++) acc[i][j] = 0.f;

    for (int kk = 0; kk < HN * KQ; kk += 16) {
        int h  = kk >> 9;
        int nb = kk & 511;
        {
            float4 v = *(const float4*)(g_P +
                (((size_t)h * NTIL + tile) * TT + ar) * KQ + nb + ac);
            As[ac + 0][ar] = v.x; As[ac + 1][ar] = v.y;
            As[ac + 2][ar] = v.z; As[ac + 3][ar] = v.w;
        }
        const float* Vp = g_qkv + (size_t)(2 * HN + h) * TDIM * CDIM;
        {
            int vrow = t0 + nb + br;
            float4 v = make_float4(0.f, 0.f, 0.f, 0.f);
            if (vrow < TDIM)
                v = *(const float4*)(Vp + (size_t)vrow * CDIM + c0 + bc);
            *(float4*)(&Bs[br][bc]) = v;
        }
        __syncthreads();
#pragma unroll
        for (int k = 0; k < 16; k++) {
            float a[4], b[4];
            *(float4*)(a) = *(const float4*)(&As[k][ty * 4]);
            *(float4*)(b) = *(const float4*)(&Bs[k][tx * 4]);
#pragma unroll
            for (int i = 0; i < 4; i++)
#pragma unroll
                for (int j = 0; j < 4; j++) acc[i][j] += a[i] * b[j];
        }
        __syncthreads();
    }

#pragma unroll
    for (int i = 0; i < 4; i++) {
        int t = t0 + ty * 4 + i;
        float* o = out + (size_t)t * CDIM + c0 + tx * 4;
        *(float4*)(o) = make_float4(acc[i][0], acc[i][1], acc[i][2], acc[i][3]);
    }
}

// ---------------------------------------------------------------------------
// Kernel 5: in-place GroupNorm.
// ---------------------------------------------------------------------------
__global__ __launch_bounds__(256) void gn_kernel(
    float* __restrict__ out,
    const float* __restrict__ wgt,
    const float* __restrict__ bias)
{
    const int t = blockIdx.x;
    const int tid = threadIdx.x;

    float4 v = *(float4*)(out + (size_t)t * CDIM + tid * 4);
    float s  = v.x + v.y + v.z + v.w;
    float sq = v.x * v.x + v.y * v.y + v.z * v.z + v.w * v.w;

#pragma unroll
    for (int off = 8; off > 0; off >>= 1) {
        s  += __shfl_down_sync(0xffffffffu, s,  off, 16);
        sq += __shfl_down_sync(0xffffffffu, sq, off, 16);
    }
    s  = __shfl_sync(0xffffffffu, s,  0, 16);
    sq = __shfl_sync(0xffffffffu, sq, 0, 16);

    float mean = s * (1.f / 64.f);
    float var  = sq * (1.f / 64.f) - mean * mean;
    float rs   = rsqrtf(var + 1e-5f);

    float4 w4 = *(const float4*)(wgt + tid * 4);
    float4 b4 = *(const float4*)(bias + tid * 4);
    v.x = (v.x - mean) * rs * w4.x + b4.x;
    v.y = (v.y - mean) * rs * w4.y + b4.y;
    v.z = (v.z - mean) * rs * w4.z + b4.z;
    v.w = (v.w - mean) * rs * w4.w + b4.w;
    *(float4*)(out + (size_t)t * CDIM + tid * 4) = v;
}

// ---------------------------------------------------------------------------
extern "C" void kernel_launch(void* const* d_in, const int* in_sizes, int n_in,
                              void* d_out, int out_size)
{
    const float* X  = (const float*)d_in[0];
    const float* Wq = (const float*)d_in[1];
    const float* Wk = (const float*)d_in[2];
    const float* Wv = (const float*)d_in[3];
    const float* gw = (const float*)d_in[4];
    const float* gb = (const float*)d_in[5];
    float* out = (float*)d_out;

    prep_x<<<(TDIM * CDIM / 4) / 256, 256>>>(X);
    prep_w<<<dim3(NW / 32, CDIM / 32, 3), dim3(32, 8)>>>(Wq, Wk, Wv);

    cudaFuncSetAttribute(proj_mma, cudaFuncAttributeMaxDynamicSharedMemorySize,
                         SMEM_PROJ);
    proj_mma<<<dim3(16, 32, 3), 256, SMEM_PROJ>>>();

    {
        size_t total = (size_t)3 * HN * TDIM * (CDIM / 2);
        rope_silu_kernel<<<(unsigned)((total + 255) / 256), 256>>>();
    }

    qk_kernel<<<dim3(4, 32, 8), 256>>>();
    av_kernel<<<dim3(16, 32), 256>>>(out);
    gn_kernel<<<TDIM, 256>>>(out, gw, gb);
}

// round 4
// speedup vs baseline: 1.9519x; 1.2659x over previous
#include <cuda_runtime.h>
#include <cuda_bf16.h>
#include <math.h>
#include <stdint.h>

#define TDIM 2048
#define CDIM 1024
#define HN   8
#define NW   8192
#define WIN  448
#define KQ   512
#define TT   64
#define NTIL 32
#define GAMMA 0.96875f

// scratch (all bf16 hi/lo split)
__device__ __nv_bfloat16 g_Xhi[(size_t)TDIM * CDIM];
__device__ __nv_bfloat16 g_Xlo[(size_t)TDIM * CDIM];
__device__ __nv_bfloat16 g_Wthi[(size_t)3 * NW * CDIM];        // [z][n][k]
__device__ __nv_bfloat16 g_Wtlo[(size_t)3 * NW * CDIM];
__device__ __nv_bfloat16 g_Qhi[(size_t)HN * TDIM * CDIM];
__device__ __nv_bfloat16 g_Qlo[(size_t)HN * TDIM * CDIM];
__device__ __nv_bfloat16 g_Khi[(size_t)HN * TDIM * CDIM];
__device__ __nv_bfloat16 g_Klo[(size_t)HN * TDIM * CDIM];
__device__ __nv_bfloat16 g_Vhi[(size_t)HN * TDIM * CDIM];      // [h][t][c]
__device__ __nv_bfloat16 g_Vlo[(size_t)HN * TDIM * CDIM];
__device__ __nv_bfloat16 g_Vthi[(size_t)HN * CDIM * TDIM];     // [h][c][t]
__device__ __nv_bfloat16 g_Vtlo[(size_t)HN * CDIM * TDIM];
__device__ __nv_bfloat16 g_Phi[(size_t)HN * NTIL * TT * KQ];   // [h][tile][t][q]
__device__ __nv_bfloat16 g_Plo[(size_t)HN * NTIL * TT * KQ];

// ---------------------------------------------------------------------------
#define CP16(dst, src) \
    asm volatile("cp.async.cg.shared.global [%0], [%1], 16;" :: "r"(dst), "l"(src))
#define CP16Z(dst, src, sz) \
    asm volatile("cp.async.cg.shared.global [%0], [%1], 16, %2;" :: "r"(dst), "l"(src), "r"(sz))
#define CP_COMMIT() asm volatile("cp.async.commit_group;" ::: "memory")
#define CP_WAIT1()  asm volatile("cp.async.wait_group 1;" ::: "memory")
#define CP_WAIT0()  asm volatile("cp.async.wait_group 0;" ::: "memory")

__device__ __forceinline__ uint32_t smem_u32(const void* p) {
    uint32_t a;
    asm("{ .reg .u64 t; cvta.to.shared.u64 t, %1; cvt.u32.u64 %0, t; }"
        : "=r"(a) : "l"(p));
    return a;
}

__device__ __forceinline__ void mma_bf16(float c[4], const uint32_t a[4],
                                         const uint32_t b[2]) {
    asm volatile(
        "mma.sync.aligned.m16n8k16.row.col.f32.bf16.bf16.f32 "
        "{%0,%1,%2,%3}, {%4,%5,%6,%7}, {%8,%9}, {%0,%1,%2,%3};"
        : "+f"(c[0]), "+f"(c[1]), "+f"(c[2]), "+f"(c[3])
        : "r"(a[0]), "r"(a[1]), "r"(a[2]), "r"(a[3]), "r"(b[0]), "r"(b[1]));
}

// split two fp32 into packed hi/lo bf16 pairs
__device__ __forceinline__ uint32_t pack_bf2(float v0, float v1, uint32_t& lo) {
    __nv_bfloat16 h0 = __float2bfloat16(v0);
    __nv_bfloat16 h1 = __float2bfloat16(v1);
    __nv_bfloat16 l0 = __float2bfloat16(v0 - __bfloat162float(h0));
    __nv_bfloat16 l1 = __float2bfloat16(v1 - __bfloat162float(h1));
    lo = (uint32_t)*(unsigned short*)&l0 | ((uint32_t)*(unsigned short*)&l1 << 16);
    return (uint32_t)*(unsigned short*)&h0 | ((uint32_t)*(unsigned short*)&h1 << 16);
}

// ---------------------------------------------------------------------------
// Prep: split X into hi/lo bf16
// ---------------------------------------------------------------------------
__global__ __launch_bounds__(256) void prep_x(const float* __restrict__ X)
{
    int i = blockIdx.x * 256 + threadIdx.x;
    float4 v = ((const float4*)X)[i];
    __nv_bfloat16 h[4], l[4];
    float f[4] = {v.x, v.y, v.z, v.w};
#pragma unroll
    for (int j = 0; j < 4; j++) {
        h[j] = __float2bfloat16(f[j]);
        l[j] = __float2bfloat16(f[j] - __bfloat162float(h[j]));
    }
    ((ushort4*)g_Xhi)[i] = make_ushort4(*(unsigned short*)&h[0], *(unsigned short*)&h[1],
                                        *(unsigned short*)&h[2], *(unsigned short*)&h[3]);
    ((ushort4*)g_Xlo)[i] = make_ushort4(*(unsigned short*)&l[0], *(unsigned short*)&l[1],
                                        *(unsigned short*)&l[2], *(unsigned short*)&l[3]);
}

// ---------------------------------------------------------------------------
// Prep: transpose W [K,N] -> Wt [N,K], split hi/lo bf16
// ---------------------------------------------------------------------------
__global__ __launch_bounds__(256) void prep_w(
    const float* __restrict__ Wq, const float* __restrict__ Wk,
    const float* __restrict__ Wv)
{
    const int z = blockIdx.z;
    const float* W = (z == 0) ? Wq : ((z == 1) ? Wk : Wv);
    const int n0 = blockIdx.x * 32;
    const int k0 = blockIdx.y * 32;

    __shared__ float t[32][33];
    const int tx = threadIdx.x, ty = threadIdx.y;
#pragma unroll
    for (int j = 0; j < 4; j++)
        t[ty + 8 * j][tx] = W[(size_t)(k0 + ty + 8 * j) * NW + n0 + tx];
    __syncthreads();
#pragma unroll
    for (int j = 0; j < 4; j++) {
        float v = t[tx][ty + 8 * j];
        __nv_bfloat16 h = __float2bfloat16(v);
        __nv_bfloat16 l = __float2bfloat16(v - __bfloat162float(h));
        size_t o = ((size_t)z * NW + n0 + ty + 8 * j) * CDIM + k0 + tx;
        g_Wthi[o] = h;
        g_Wtlo[o] = l;
    }
}

// ---------------------------------------------------------------------------
// Projection via mma.sync bf16 3-term split, fused RoPE+SiLU epilogue,
// output hi/lo bf16 (Q/K/V).  CTA tile M=128, N=256, K-stage 32.
// ---------------------------------------------------------------------------
#define PSTAGE 61440
#define SMEM_PROJ (2 * PSTAGE)

__device__ __forceinline__ void proj_load_stage(
    uint32_t stb, int tid, int m0, int zn0, int k0)
{
#pragma unroll
    for (int i = 0; i < 12; i++) {
        const int c = tid + i * 256;
        if (c < 1024) {
            const int mat = c >> 9;
            const int rem = c & 511;
            const int row = rem >> 2;
            const int ch  = rem & 3;
            const __nv_bfloat16* src = (mat ? g_Xlo : g_Xhi)
                + (size_t)(m0 + row) * CDIM + k0 + ch * 8;
            CP16(stb + mat * 10240 + row * 80 + ch * 16, src);
        } else {
            const int cb  = c - 1024;
            const int mat = cb >> 10;
            const int rem = cb & 1023;
            const int row = rem >> 2;
            const int ch  = rem & 3;
            const __nv_bfloat16* src = (mat ? g_Wtlo : g_Wthi)
                + (size_t)(zn0 + row) * CDIM + k0 + ch * 8;
            CP16(stb + 20480 + mat * 20480 + row * 80 + ch * 16, src);
        }
    }
}

__global__ __launch_bounds__(256, 1) void proj_mma()
{
    extern __shared__ char smem[];
    const uint32_t sb = smem_u32(smem);
    const int tid = threadIdx.x;
    const int wid = tid >> 5;
    const int lane = tid & 31;
    const int wm = wid & 1, wn = wid >> 1;
    const int g = lane >> 2, t4 = lane & 3;

    const int m0 = blockIdx.x * 128;
    const int n0 = blockIdx.y * 256;
    const int z  = blockIdx.z;
    const int zn0 = z * NW + n0;

    float acc[4][8][4];
#pragma unroll
    for (int i = 0; i < 4; i++)
#pragma unroll
        for (int j = 0; j < 8; j++)
#pragma unroll
            for (int q = 0; q < 4; q++) acc[i][j][q] = 0.f;

    proj_load_stage(sb, tid, m0, zn0, 0);
    CP_COMMIT();

#pragma unroll 1
    for (int s = 0; s < 32; s++) {
        const char* st = smem + (s & 1) * PSTAGE;
        if (s + 1 < 32) {
            proj_load_stage(sb + ((s + 1) & 1) * PSTAGE, tid, m0, zn0, (s + 1) * 32);
            CP_COMMIT();
            CP_WAIT1();
        } else {
            CP_WAIT0();
        }
        __syncthreads();

        const char* Ah = st;
        const char* Al = st + 10240;
        const char* Bh = st + 20480;
        const char* Bl = st + 40960;

#pragma unroll
        for (int kk = 0; kk < 32; kk += 16) {
            uint32_t ah[4][4], al[4][4];
#pragma unroll
            for (int i = 0; i < 4; i++) {
                const int b0 = (wm * 64 + i * 16 + g) * 80 + kk * 2 + t4 * 4;
                ah[i][0] = *(const uint32_t*)(Ah + b0);
                ah[i][1] = *(const uint32_t*)(Ah + b0 + 640);
                ah[i][2] = *(const uint32_t*)(Ah + b0 + 16);
                ah[i][3] = *(const uint32_t*)(Ah + b0 + 656);
                al[i][0] = *(const uint32_t*)(Al + b0);
                al[i][1] = *(const uint32_t*)(Al + b0 + 640);
                al[i][2] = *(const uint32_t*)(Al + b0 + 16);
                al[i][3] = *(const uint32_t*)(Al + b0 + 656);
            }
#pragma unroll
            for (int jj = 0; jj < 2; jj++) {
                uint32_t bh[4][2], bl[4][2];
#pragma unroll
                for (int j = 0; j < 4; j++) {
                    const int bb = (wn * 64 + jj * 32 + j * 8 + g) * 80 + kk * 2 + t4 * 4;
                    bh[j][0] = *(const uint32_t*)(Bh + bb);
                    bh[j][1] = *(const uint32_t*)(Bh + bb + 16);
                    bl[j][0] = *(const uint32_t*)(Bl + bb);
                    bl[j][1] = *(const uint32_t*)(Bl + bb + 16);
                }
#pragma unroll
                for (int i = 0; i < 4; i++)
#pragma unroll
                    for (int j = 0; j < 4; j++) {
                        float* c = acc[i][jj * 4 + j];
                        mma_bf16(c, ah[i], bh[j]);
                        mma_bf16(c, ah[i], bl[j]);
                        mma_bf16(c, al[i], bh[j]);
                    }
            }
        }
        __syncthreads();
    }

    // epilogue: RoPE (Q,K cols<64) + SiLU, split hi/lo bf16, store
    const int h  = n0 >> 10;
    const int cbase = (n0 & 1023) + wn * 64 + 2 * t4;
    const bool rope_blk = (z < 2) && ((n0 & 1023) == 0) && (wn == 0);

    __nv_bfloat16* Hi = (z == 0) ? g_Qhi : ((z == 1) ? g_Khi : g_Vhi);
    __nv_bfloat16* Lo = (z == 0) ? g_Qlo : ((z == 1) ? g_Klo : g_Vlo);
    Hi += (size_t)h * TDIM * CDIM;
    Lo += (size_t)h * TDIM * CDIM;

#pragma unroll
    for (int i = 0; i < 4; i++) {
#pragma unroll
        for (int rr = 0; rr < 2; rr++) {
            const int r = m0 + wm * 64 + i * 16 + g + rr * 8;
#pragma unroll
            for (int j = 0; j < 8; j++) {
                const int col = cbase + j * 8;
                float v0 = acc[i][j][2 * rr];
                float v1 = acc[i][j][2 * rr + 1];
                if (rope_blk) {
                    int c2 = col >> 1;
                    float invf = (float)exp(-((double)(2 * c2) / 64.0) * log(10000.0));
                    float ang = (float)r * invf;
                    float sn, cs;
                    sincosf(ang, &sn, &cs);
                    float y0 = v0 * cs - v1 * sn;
                    float y1 = v1 * cs + v0 * sn;
                    v0 = y0; v1 = y1;
                }
                v0 = v0 / (1.f + expf(-v0));
                v1 = v1 / (1.f + expf(-v1));
                uint32_t lo, hi = pack_bf2(v0, v1, lo);
                size_t idx = ((size_t)r * CDIM + col) >> 1;   // u32 index
                ((uint32_t*)Hi)[idx] = hi;
                ((uint32_t*)Lo)[idx] = lo;
            }
        }
    }
}

// ---------------------------------------------------------------------------
// V transpose: [h][t][c] -> [h][c][t] (hi & lo)
// ---------------------------------------------------------------------------
__global__ void transpose_v()
{
    __shared__ unsigned short sh[32][33], sl[32][33];
    const int c0 = blockIdx.x * 32;
    const int t0 = blockIdx.y * 32;
    const int h  = blockIdx.z;
    const int tx = threadIdx.x, ty = threadIdx.y;

    const unsigned short* Vh = (const unsigned short*)g_Vhi + (size_t)h * TDIM * CDIM;
    const unsigned short* Vl = (const unsigned short*)g_Vlo + (size_t)h * TDIM * CDIM;
#pragma unroll
    for (int k = 0; k < 4; k++) {
        int r = ty + 8 * k;
        sh[r][tx] = Vh[(size_t)(t0 + r) * CDIM + c0 + tx];
        sl[r][tx] = Vl[(size_t)(t0 + r) * CDIM + c0 + tx];
    }
    __syncthreads();
    unsigned short* Th = (unsigned short*)g_Vthi + (size_t)h * CDIM * TDIM;
    unsigned short* Tl = (unsigned short*)g_Vtlo + (size_t)h * CDIM * TDIM;
#pragma unroll
    for (int k = 0; k < 4; k++) {
        int r = ty + 8 * k;
        Th[(size_t)(c0 + r) * TDIM + t0 + tx] = sh[tx][r];
        Tl[(size_t)(c0 + r) * TDIM + t0 + tx] = sl[tx][r];
    }
}

// ---------------------------------------------------------------------------
// qk_mma: banded scores P = decay * (K Q^T), bf16 split, M=64(t) N=256(q) K=1024
// smem stage: Ah@0(5120) Al@5120 Bh@10240(20480) Bl@30720; stage 51200 x2
// ---------------------------------------------------------------------------
#define QKSTAGE 51200
#define SMEM_QK (2 * QKSTAGE)

__global__ __launch_bounds__(256, 1) void qk_mma()
{
    extern __shared__ char smem[];
    const uint32_t sb = smem_u32(smem);
    const int tid = threadIdx.x;
    const int wid = tid >> 5;
    const int lane = tid & 31;
    const int wm = wid & 1, wn = wid >> 1;
    const int g = lane >> 2, t4 = lane & 3;

    const int qc   = blockIdx.x;          // 0..1
    const int tile = blockIdx.y;
    const int h    = blockIdx.z;
    const int t0   = tile * TT;
    const int q0   = t0 + qc * 256;

    const __nv_bfloat16* Kh = g_Khi + (size_t)h * TDIM * CDIM;
    const __nv_bfloat16* Kl = g_Klo + (size_t)h * TDIM * CDIM;
    const __nv_bfloat16* Qh = g_Qhi + (size_t)h * TDIM * CDIM;
    const __nv_bfloat16* Ql = g_Qlo + (size_t)h * TDIM * CDIM;

    float acc[2][8][4];
#pragma unroll
    for (int i = 0; i < 2; i++)
#pragma unroll
        for (int j = 0; j < 8; j++)
#pragma unroll
            for (int q = 0; q < 4; q++) acc[i][j][q] = 0.f;

    auto load_stage = [&](int s, uint32_t stb) {
        const int k0 = s * 32;
#pragma unroll
        for (int i = 0; i < 10; i++) {
            const int c = tid + i * 256;
            if (c < 512) {
                const int mat = c >> 8, rem = c & 255;
                const int row = rem >> 2, ch = rem & 3;
                const __nv_bfloat16* src = (mat ? Kl : Kh)
                    + (size_t)(t0 + row) * CDIM + k0 + ch * 8;
                CP16(stb + mat * 5120 + row * 80 + ch * 16, src);
            } else {
                const int cb = c - 512;
                const int mat = cb >> 10, rem = cb & 1023;
                const int row = rem >> 2, ch = rem & 3;
                int q = q0 + row;
                int sz = (q < TDIM) ? 16 : 0;
                if (q >= TDIM) q = 0;
                const __nv_bfloat16* src = (mat ? Ql : Qh)
                    + (size_t)q * CDIM + k0 + ch * 8;
                CP16Z(stb + 10240 + mat * 20480 + row * 80 + ch * 16, src, sz);
            }
        }
    };

    load_stage(0, sb);
    CP_COMMIT();

#pragma unroll 1
    for (int s = 0; s < 32; s++) {
        const char* st = smem + (s & 1) * QKSTAGE;
        if (s + 1 < 32) {
            load_stage(s + 1, sb + ((s + 1) & 1) * QKSTAGE);
            CP_COMMIT();
            CP_WAIT1();
        } else {
            CP_WAIT0();
        }
        __syncthreads();

        const char* Ah = st;
        const char* Al = st + 5120;
        const char* Bh = st + 10240;
        const char* Bl = st + 30720;

#pragma unroll
        for (int kk = 0; kk < 32; kk += 16) {
            uint32_t ah[2][4], al[2][4];
#pragma unroll
            for (int i = 0; i < 2; i++) {
                const int b0 = (wm * 32 + i * 16 + g) * 80 + kk * 2 + t4 * 4;
                ah[i][0] = *(const uint32_t*)(Ah + b0);
                ah[i][1] = *(const uint32_t*)(Ah + b0 + 640);
                ah[i][2] = *(const uint32_t*)(Ah + b0 + 16);
                ah[i][3] = *(const uint32_t*)(Ah + b0 + 656);
                al[i][0] = *(const uint32_t*)(Al + b0);
                al[i][1] = *(const uint32_t*)(Al + b0 + 640);
                al[i][2] = *(const uint32_t*)(Al + b0 + 16);
                al[i][3] = *(const uint32_t*)(Al + b0 + 656);
            }
#pragma unroll
            for (int jj = 0; jj < 2; jj++) {
                uint32_t bh[4][2], bl[4][2];
#pragma unroll
                for (int j = 0; j < 4; j++) {
                    const int bb = (wn * 64 + jj * 32 + j * 8 + g) * 80 + kk * 2 + t4 * 4;
                    bh[j][0] = *(const uint32_t*)(Bh + bb);
                    bh[j][1] = *(const uint32_t*)(Bh + bb + 16);
                    bl[j][0] = *(const uint32_t*)(Bl + bb);
                    bl[j][1] = *(const uint32_t*)(Bl + bb + 16);
                }
#pragma unroll
                for (int i = 0; i < 2; i++)
#pragma unroll
                    for (int j = 0; j < 4; j++) {
                        float* c = acc[i][jj * 4 + j];
                        mma_bf16(c, ah[i], bh[j]);
                        mma_bf16(c, ah[i], bl[j]);
                        mma_bf16(c, al[i], bh[j]);
                    }
            }
        }
        __syncthreads();
    }

    // epilogue: decay + mask, split hi/lo, store P
    const float lg = log2f(GAMMA);
    __nv_bfloat16* Phb = g_Phi + ((size_t)h * NTIL + tile) * TT * KQ;
    __nv_bfloat16* Plb = g_Plo + ((size_t)h * NTIL + tile) * TT * KQ;
#pragma unroll
    for (int i = 0; i < 2; i++) {
#pragma unroll
        for (int rr = 0; rr < 2; rr++) {
            const int tl = wm * 32 + i * 16 + g + rr * 8;
            const int t  = t0 + tl;
#pragma unroll
            for (int j = 0; j < 8; j++) {
                const int ql = qc * 256 + wn * 64 + j * 8 + 2 * t4;
                const int q  = t0 + ql;
                float v0 = acc[i][j][2 * rr];
                float v1 = acc[i][j][2 * rr + 1];
                int wd0 = q - t, wd1 = wd0 + 1;
                v0 = (wd0 >= 0 && wd0 < WIN && q < TDIM)
                     ? v0 * exp2f((float)wd0 * lg) : 0.f;
                v1 = (wd1 >= 0 && wd1 < WIN && (q + 1) < TDIM)
                     ? v1 * exp2f((float)wd1 * lg) : 0.f;
                uint32_t lo, hi = pack_bf2(v0, v1, lo);
                size_t idx = ((size_t)tl * KQ + ql) >> 1;
                ((uint32_t*)Phb)[idx] = hi;
                ((uint32_t*)Plb)[idx] = lo;
            }
        }
    }
}

// ---------------------------------------------------------------------------
// av_mma: out[t][c] = sum_{h,q} P[h,tile,t,q] * V[h, t0+q, c]
// M=64(t) N=128(c) K=4096; A=P (hi/lo), B=V_T [h][c][t] (hi/lo)
// smem stage: Ah@0(5120) Al@5120 Bh@10240(10240) Bl@20480; stage 30720 x2
// ---------------------------------------------------------------------------
#define AVSTAGE 30720
#define SMEM_AV (2 * AVSTAGE)

__global__ __launch_bounds__(256, 1) void av_mma(float* __restrict__ out)
{
    extern __shared__ char smem[];
    const uint32_t sb = smem_u32(smem);
    const int tid = threadIdx.x;
    const int wid = tid >> 5;
    const int lane = tid & 31;
    const int wm = wid & 1, wn = wid >> 1;
    const int g = lane >> 2, t4 = lane & 3;

    const int cc   = blockIdx.x;      // 0..7
    const int tile = blockIdx.y;
    const int t0   = tile * TT;
    const int c0   = cc * 128;

    float acc[2][4][4];
#pragma unroll
    for (int i = 0; i < 2; i++)
#pragma unroll
        for (int j = 0; j < 4; j++)
#pragma unroll
            for (int q = 0; q < 4; q++) acc[i][j][q] = 0.f;

    auto load_stage = [&](int s, uint32_t stb) {
        const int kk0 = s * 32;
        const int h   = kk0 >> 9;
        const int ql  = kk0 & 511;
#pragma unroll
        for (int i = 0; i < 6; i++) {
            const int c = tid + i * 256;
            if (c < 512) {
                const int mat = c >> 8, rem = c & 255;
                const int row = rem >> 2, ch = rem & 3;
                const __nv_bfloat16* src = (mat ? g_Plo : g_Phi)
                    + ((size_t)h * NTIL + tile) * TT * KQ
                    + (size_t)row * KQ + ql + ch * 8;
                CP16(stb + mat * 5120 + row * 80 + ch * 16, src);
            } else {
                const int cb = c - 512;
                const int mat = cb >> 9, rem = cb & 511;
                const int row = rem >> 2, ch = rem & 3;
                int tg = t0 + ql + ch * 8;
                int sz = (tg < TDIM) ? 16 : 0;
                if (tg >= TDIM) tg = 0;
                const __nv_bfloat16* src = (mat ? g_Vtlo : g_Vthi)
                    + ((size_t)h * CDIM + c0 + row) * TDIM + tg;
                CP16Z(stb + 10240 + mat * 10240 + row * 80 + ch * 16, src, sz);
            }
        }
    };

    load_stage(0, sb);
    CP_COMMIT();

#pragma unroll 1
    for (int s = 0; s < 128; s++) {
        const char* st = smem + (s & 1) * AVSTAGE;
        if (s + 1 < 128) {
            load_stage(s + 1, sb + ((s + 1) & 1) * AVSTAGE);
            CP_COMMIT();
            CP_WAIT1();
        } else {
            CP_WAIT0();
        }
        __syncthreads();

        const char* Ah = st;
        const char* Al = st + 5120;
        const char* Bh = st + 10240;
        const char* Bl = st + 20480;

#pragma unroll
        for (int kk = 0; kk < 32; kk += 16) {
            uint32_t ah[2][4], al[2][4];
#pragma unroll
            for (int i = 0; i < 2; i++) {
                const int b0 = (wm * 32 + i * 16 + g) * 80 + kk * 2 + t4 * 4;
                ah[i][0] = *(const uint32_t*)(Ah + b0);
                ah[i][1] = *(const uint32_t*)(Ah + b0 + 640);
                ah[i][2] = *(const uint32_t*)(Ah + b0 + 16);
                ah[i][3] = *(const uint32_t*)(Ah + b0 + 656);
                al[i][0] = *(const uint32_t*)(Al + b0);
                al[i][1] = *(const uint32_t*)(Al + b0 + 640);
                al[i][2] = *(const uint32_t*)(Al + b0 + 16);
                al[i][3] = *(const uint32_t*)(Al + b0 + 656);
            }
            uint32_t bh[4][2], bl[4][2];
#pragma unroll
            for (int j = 0; j < 4; j++) {
                const int bb = (wn * 32 + j * 8 + g) * 80 + kk * 2 + t4 * 4;
                bh[j][0] = *(const uint32_t*)(Bh + bb);
                bh[j][1] = *(const uint32_t*)(Bh + bb + 16);
                bl[j][0] = *(const uint32_t*)(Bl + bb);
                bl[j][1] = *(const uint32_t*)(Bl + bb + 16);
            }
#pragma unroll
            for (int i = 0; i < 2; i++)
#pragma unroll
                for (int j = 0; j < 4; j++) {
                    float* c = acc[i][j];
                    mma_bf16(c, ah[i], bh[j]);
                    mma_bf16(c, ah[i], bl[j]);
                    mma_bf16(c, al[i], bh[j]);
                }
        }
        __syncthreads();
    }

    // epilogue: fp32 out
#pragma unroll
    for (int i = 0; i < 2; i++) {
#pragma unroll
        for (int rr = 0; rr < 2; rr++) {
            const int t = t0 + wm * 32 + i * 16 + g + rr * 8;
#pragma unroll
            for (int j = 0; j < 4; j++) {
                const int c = c0 + wn * 32 + j * 8 + 2 * t4;
                *(float2*)(out + (size_t)t * CDIM + c) =
                    make_float2(acc[i][j][2 * rr], acc[i][j][2 * rr + 1]);
            }
        }
    }
}

// ---------------------------------------------------------------------------
// GroupNorm in place on out
// ---------------------------------------------------------------------------
__global__ __launch_bounds__(256) void gn_kernel(
    float* __restrict__ out,
    const float* __restrict__ wgt,
    const float* __restrict__ bias)
{
    const int t = blockIdx.x;
    const int tid = threadIdx.x;

    float4 v = *(float4*)(out + (size_t)t * CDIM + tid * 4);
    float s  = v.x + v.y + v.z + v.w;
    float sq = v.x * v.x + v.y * v.y + v.z * v.z + v.w * v.w;

#pragma unroll
    for (int off = 8; off > 0; off >>= 1) {
        s  += __shfl_down_sync(0xffffffffu, s,  off, 16);
        sq += __shfl_down_sync(0xffffffffu, sq, off, 16);
    }
    s  = __shfl_sync(0xffffffffu, s,  0, 16);
    sq = __shfl_sync(0xffffffffu, sq, 0, 16);

    float mean = s * (1.f / 64.f);
    float var  = sq * (1.f / 64.f) - mean * mean;
    float rs   = rsqrtf(var + 1e-5f);

    float4 w4 = *(const float4*)(wgt + tid * 4);
    float4 b4 = *(const float4*)(bias + tid * 4);
    v.x = (v.x - mean) * rs * w4.x + b4.x;
    v.y = (v.y - mean) * rs * w4.y + b4.y;
    v.z = (v.z - mean) * rs * w4.z + b4.z;
    v.w = (v.w - mean) * rs * w4.w + b4.w;
    *(float4*)(out + (size_t)t * CDIM + tid * 4) = v;
}

// ---------------------------------------------------------------------------
extern "C" void kernel_launch(void* const* d_in, const int* in_sizes, int n_in,
                              void* d_out, int out_size)
{
    const float* X  = (const float*)d_in[0];
    const float* Wq = (const float*)d_in[1];
    const float* Wk = (const float*)d_in[2];
    const float* Wv = (const float*)d_in[3];
    const float* gw = (const float*)d_in[4];
    const float* gb = (const float*)d_in[5];
    float* out = (float*)d_out;

    prep_x<<<(TDIM * CDIM / 4) / 256, 256>>>(X);
    prep_w<<<dim3(NW / 32, CDIM / 32, 3), dim3(32, 8)>>>(Wq, Wk, Wv);

    cudaFuncSetAttribute(proj_mma, cudaFuncAttributeMaxDynamicSharedMemorySize,
                         SMEM_PROJ);
    proj_mma<<<dim3(16, 32, 3), 256, SMEM_PROJ>>>();

    transpose_v<<<dim3(CDIM / 32, TDIM / 32, HN), dim3(32, 8)>>>();

    cudaFuncSetAttribute(qk_mma, cudaFuncAttributeMaxDynamicSharedMemorySize,
                         SMEM_QK);
    qk_mma<<<dim3(2, NTIL, HN), 256, SMEM_QK>>>();

    cudaFuncSetAttribute(av_mma, cudaFuncAttributeMaxDynamicSharedMemorySize,
                         SMEM_AV);
    av_mma<<<dim3(8, NTIL), 256, SMEM_AV>>>(out);

    gn_kernel<<<TDIM, 256>>>(out, gw, gb);
}